// round 2
// baseline (speedup 1.0000x reference)
#include <cuda_runtime.h>
#include <math.h>
#include <stdint.h>

// Problem dims
#define BB   2048
#define DD   256
#define HH   512
#define NSLOT 64
#define FEAT 513
#define G4   2048   // 4*H

// Output layout offsets (float32 elements)
#define OFF_H      ((size_t)0)
#define OFF_C      ((size_t)1048576)
#define OFF_HMEM   ((size_t)2097152)
#define OFF_SLOTS  ((size_t)3145728)
#define OFF_CUM    ((size_t)36700160)
#define OFF_DELTA  ((size_t)70254592)
#define OFF_FILLED ((size_t)70385664)

// ------------------------------- scratch ------------------------------------
__device__ float g_q[BB * HH];
__device__ float g_kq[BB * DD];
__device__ float g_v[BB * DD];
__device__ int   g_idx[BB];
__device__ float g_bias[G4];
__device__ float g_mem[(size_t)NSLOT * BB * FEAT];   // mem_seq, layout [n][b][f]
__device__ float g_xg[(size_t)NSLOT * BB * G4];      // input projections [n][b][g]
__device__ float g_gates[(size_t)BB * G4];
__device__ float g_h[BB * HH];
__device__ float g_c[BB * HH];
__device__ int   g_fmode;                            // 0=f32,1=i32,2=u8,3=bf16

__device__ __forceinline__ float sigf(float x) { return 1.0f / (1.0f + expf(-x)); }

__device__ __forceinline__ int read_filled(const void* p, size_t i, int m) {
    if (m == 0) return ((const float*)p)[i] != 0.0f;
    if (m == 1) return ((const int*)p)[i] != 0;
    if (m == 2) return ((const unsigned char*)p)[i] != 0;
    return ((const unsigned short*)p)[i] != 0;   // bf16 bits
}

// ------------------------- dtype detection for `filled` ----------------------
__global__ void detect_filled_kernel(const unsigned int* __restrict__ w) {
    __shared__ int flags[3];  // [0]=saw 1.0f word, [1]=saw bf16 pair, [2]=saw other >1
    if (threadIdx.x < 3) flags[threadIdx.x] = 0;
    __syncthreads();
    // Smallest possible buffer: uint8 -> B*N bytes = 32768 words. Scan exactly that.
    for (int i = threadIdx.x; i < (BB * NSLOT) / 4; i += blockDim.x) {
        unsigned v = w[i];
        if (v == 0x3F800000u)      atomicOr(&flags[0], 1);
        else if (v == 0x3F803F80u) atomicOr(&flags[1], 1);
        else if (v > 1u)           atomicOr(&flags[2], 1);
    }
    __syncthreads();
    if (threadIdx.x == 0) {
        int m;
        if (flags[1])      m = 3;   // bf16 (pair 1,1 appears)
        else if (flags[0]) m = 0;   // float32
        else if (flags[2]) m = 2;   // packed uint8 bools
        else               m = 1;   // int32 (words only 0/1)
        g_fmode = m;
    }
}

// ------------------------------- small utils --------------------------------
__global__ void zero_hc_kernel() {
    int e = blockIdx.x * blockDim.x + threadIdx.x;
    if (e < BB * HH) { g_h[e] = 0.0f; g_c[e] = 0.0f; }
}

__global__ void combine_bias_kernel(const float* __restrict__ bih,
                                    const float* __restrict__ bhh) {
    int e = blockIdx.x * blockDim.x + threadIdx.x;
    if (e < G4) g_bias[e] = bih[e] + bhh[e];
}

// ------------------------------- SGEMM --------------------------------------
// C[m,n] = sum_k A[m,k] * W(n,k) [+ bias[n]] [+ Cin[m,n]]
// wTrans=1: W stored (N,K) row-major (i.e. A @ W.T) ; wTrans=0: W stored (K,N).
__global__ void __launch_bounds__(256)
sgemm_kernel(int M, int N, int K,
             const float* __restrict__ A, int lda,
             const float* __restrict__ W, int ldw, int wTrans,
             float* __restrict__ C, int ldc,
             const float* __restrict__ bias,
             const float* __restrict__ Cin) {
    __shared__ __align__(16) float As[16][128];
    __shared__ __align__(16) float Ws[16][128];

    const int tid = threadIdx.x;
    const int tx = tid & 15;         // 16 col-groups
    const int ty = tid >> 4;         // 16 row-groups
    const int bm = blockIdx.y * 128;
    const int bn = blockIdx.x * 128;

    float acc[8][8];
#pragma unroll
    for (int i = 0; i < 8; i++)
#pragma unroll
        for (int j = 0; j < 8; j++) acc[i][j] = 0.0f;

    for (int k0 = 0; k0 < K; k0 += 16) {
#pragma unroll
        for (int l = tid; l < 2048; l += 256) {
            int m = l >> 4, k = l & 15;
            int gm = bm + m, gk = k0 + k;
            As[k][m] = (gm < M && gk < K) ? A[(size_t)gm * lda + gk] : 0.0f;
        }
        if (wTrans) {
#pragma unroll
            for (int l = tid; l < 2048; l += 256) {
                int n = l >> 4, k = l & 15;
                int gn = bn + n, gk = k0 + k;
                Ws[k][n] = (gn < N && gk < K) ? W[(size_t)gn * ldw + gk] : 0.0f;
            }
        } else {
#pragma unroll
            for (int l = tid; l < 2048; l += 256) {
                int n = l >> 4, k = l & 15;
                int gn = bn + n, gk = k0 + k;
                Ws[k][n] = (gn < N && gk < K) ? W[(size_t)gk * ldw + gn] : 0.0f;
            }
        }
        __syncthreads();
#pragma unroll
        for (int k = 0; k < 16; k++) {
            float4 a0 = *(const float4*)&As[k][ty * 8];
            float4 a1 = *(const float4*)&As[k][ty * 8 + 4];
            float4 w0 = *(const float4*)&Ws[k][tx * 8];
            float4 w1 = *(const float4*)&Ws[k][tx * 8 + 4];
            float a[8] = {a0.x, a0.y, a0.z, a0.w, a1.x, a1.y, a1.z, a1.w};
            float w[8] = {w0.x, w0.y, w0.z, w0.w, w1.x, w1.y, w1.z, w1.w};
#pragma unroll
            for (int i = 0; i < 8; i++)
#pragma unroll
                for (int j = 0; j < 8; j++) acc[i][j] = fmaf(a[i], w[j], acc[i][j]);
        }
        __syncthreads();
    }

#pragma unroll
    for (int i = 0; i < 8; i++) {
        int gm = bm + ty * 8 + i;
        if (gm >= M) continue;
#pragma unroll
        for (int j = 0; j < 8; j++) {
            int gn = bn + tx * 8 + j;
            if (gn >= N) continue;
            float v = acc[i][j];
            if (bias) v += bias[gn];
            if (Cin) v += Cin[(size_t)gm * ldc + gn];
            C[(size_t)gm * ldc + gn] = v;
        }
    }
}

static inline void launch_sgemm(int M, int N, int K,
                                const float* A, int lda,
                                const float* W, int ldw, int wTrans,
                                float* C, int ldc,
                                const float* bias, const float* Cin) {
    dim3 grid((N + 127) / 128, (M + 127) / 128);
    sgemm_kernel<<<grid, 256>>>(M, N, K, A, lda, W, ldw, wTrans, C, ldc, bias, Cin);
}

// --------------------------- slot index selection ----------------------------
__global__ void select_idx_kernel(const float* __restrict__ slots,
                                  const void* __restrict__ filled) {
    const int b = blockIdx.x;
    const int t = threadIdx.x;  // 64 threads, one per slot
    __shared__ float kq_s[DD];
    __shared__ float sims[NSLOT];
    __shared__ int   emp[NSLOT];
    for (int d = t; d < DD; d += NSLOT) kq_s[d] = g_kq[b * DD + d];
    __syncthreads();
    const float* sp = slots + ((size_t)b * NSLOT + t) * DD;
    float s = 0.0f;
    for (int d = 0; d < DD; d++) s = fmaf(sp[d], kq_s[d], s);
    sims[t] = s;
    emp[t]  = !read_filled(filled, (size_t)b * NSLOT + t, g_fmode);
    __syncthreads();
    if (t == 0) {
        int idx = -1;
        for (int n = 0; n < NSLOT; n++) if (emp[n]) { idx = n; break; }
        if (idx < 0) {
            float best = sims[0]; idx = 0;
            for (int n = 1; n < NSLOT; n++) if (sims[n] > best) { best = sims[n]; idx = n; }
        }
        g_idx[b] = idx;
    }
}

// --------------------- slot update + output write + mem_seq ------------------
__global__ void update_write_kernel(const float* __restrict__ slots,
                                    const float* __restrict__ cum,
                                    const float* __restrict__ delta,
                                    const void* __restrict__ filled,
                                    const float* __restrict__ x,
                                    float* __restrict__ out) {
    size_t e = (size_t)blockIdx.x * blockDim.x + threadIdx.x;
    if (e >= (size_t)BB * NSLOT * DD) return;
    int d = (int)(e % DD);
    size_t bn = e / DD;
    int n = (int)(bn % NSLOT);
    int b = (int)(bn / NSLOT);
    int idx = g_idx[b];

    float xv = x[b * DD + d];
    float sl = slots[e];
    float cf = cum[e] + xv;
    if (n == idx) { sl = g_v[b * DD + d]; cf = xv; }

    out[OFF_SLOTS + e] = sl;
    out[OFF_CUM + e]   = cf;

    size_t mbase = ((size_t)n * BB + b) * FEAT;
    g_mem[mbase + d]      = sl;
    g_mem[mbase + DD + d] = cf;

    if (d == 0) {
        float dt = (n == idx) ? 0.0f : delta[bn] + 1.0f;
        out[OFF_DELTA + bn] = dt;
        g_mem[mbase + 2 * DD] = dt;
        int fl = (n == idx) ? 1 : read_filled(filled, bn, g_fmode);
        out[OFF_FILLED + bn] = fl ? 1.0f : 0.0f;
    }
}

// --------------------------- LSTM pointwise steps ---------------------------
__global__ void step_pointwise_kernel() {
    int e = blockIdx.x * blockDim.x + threadIdx.x;
    if (e >= BB * HH) return;
    int b = e / HH, j = e % HH;
    size_t base = (size_t)b * G4 + j;
    float i = sigf(g_gates[base]);
    float f = sigf(g_gates[base + HH]);
    float g = tanhf(g_gates[base + 2 * HH]);
    float o = sigf(g_gates[base + 3 * HH]);
    float c = f * g_c[e] + i * g;
    g_c[e] = c;
    g_h[e] = o * tanhf(c);
}

__global__ void outer_pointwise_kernel(const float* __restrict__ c_in,
                                       float* __restrict__ out) {
    int e = blockIdx.x * blockDim.x + threadIdx.x;
    if (e >= BB * HH) return;
    int b = e / HH, j = e % HH;
    size_t base = (size_t)b * G4 + j;
    float i = sigf(g_gates[base]);
    float f = sigf(g_gates[base + HH]);
    float g = tanhf(g_gates[base + 2 * HH]);
    float o = sigf(g_gates[base + 3 * HH]);
    float c = f * c_in[e] + i * g;
    out[OFF_C + e] = c;
    out[OFF_H + e] = o * tanhf(c);
    out[OFF_HMEM + e] = g_h[e];   // h_mem (final slot-LSTM hidden)
}

// --------------------------------- launch -----------------------------------
extern "C" void kernel_launch(void* const* d_in, const int* in_sizes, int n_in,
                              void* d_out, int out_size) {
    const float* x_t      = (const float*)d_in[0];
    const float* h_lstm   = (const float*)d_in[1];
    const float* c_lstm   = (const float*)d_in[2];
    // d_in[3] = h_mem_prev: unused by the reference
    const float* slots    = (const float*)d_in[4];
    const float* cum      = (const float*)d_in[5];
    const float* delta    = (const float*)d_in[6];
    const void*  filled   = (const void*)d_in[7];
    const float* Wq       = (const float*)d_in[8];
    const float* Wk       = (const float*)d_in[9];
    const float* Wv       = (const float*)d_in[10];
    const float* bv       = (const float*)d_in[11];
    const float* lstm_Wih = (const float*)d_in[12];
    const float* lstm_Whh = (const float*)d_in[13];
    const float* lstm_bih = (const float*)d_in[14];
    const float* lstm_bhh = (const float*)d_in[15];
    const float* W_ih     = (const float*)d_in[16];
    const float* b_ih     = (const float*)d_in[17];
    const float* W_hh     = (const float*)d_in[18];
    float* out = (float*)d_out;

    // Resolve scratch addresses
    float *p_q, *p_kq, *p_v, *p_mem, *p_xg, *p_gates, *p_h, *p_c, *p_bias;
    cudaGetSymbolAddress((void**)&p_q, g_q);
    cudaGetSymbolAddress((void**)&p_kq, g_kq);
    cudaGetSymbolAddress((void**)&p_v, g_v);
    cudaGetSymbolAddress((void**)&p_mem, g_mem);
    cudaGetSymbolAddress((void**)&p_xg, g_xg);
    cudaGetSymbolAddress((void**)&p_gates, g_gates);
    cudaGetSymbolAddress((void**)&p_h, g_h);
    cudaGetSymbolAddress((void**)&p_c, g_c);
    cudaGetSymbolAddress((void**)&p_bias, g_bias);

    // 0) detect `filled` dtype, init recurrent state, combined slot-LSTM bias
    detect_filled_kernel<<<1, 256>>>((const unsigned int*)filled);
    zero_hc_kernel<<<(BB * HH + 255) / 256, 256>>>();
    combine_bias_kernel<<<(G4 + 255) / 256, 256>>>(lstm_bih, lstm_bhh);

    // 1) q = x @ Wq.T ; kq = q @ Wk ; v = x @ Wv.T + bv
    launch_sgemm(BB, HH, DD, x_t, DD, Wq, DD, 1, p_q, HH, nullptr, nullptr);
    launch_sgemm(BB, DD, HH, p_q, HH, Wk, DD, 0, p_kq, DD, nullptr, nullptr);
    launch_sgemm(BB, DD, DD, x_t, DD, Wv, DD, 1, p_v, DD, bv, nullptr);

    // 2) slot index selection (first-empty else argmax sims)
    select_idx_kernel<<<BB, NSLOT>>>(slots, filled);

    // 3) slot/cum/delta/filled update -> outputs + mem_seq [n][b][f]
    {
        size_t tot = (size_t)BB * NSLOT * DD;
        update_write_kernel<<<(unsigned)((tot + 255) / 256), 256>>>(
            slots, cum, delta, filled, x_t, out);
    }

    // 4) xg[n,b,:] = mem_seq[n,b,:] @ Wih.T + (bih+bhh)   (M=131072,N=2048,K=513)
    launch_sgemm(NSLOT * BB, G4, FEAT, p_mem, FEAT, lstm_Wih, FEAT, 1,
                 p_xg, G4, p_bias, nullptr);

    // 5) recurrence over 64 slots
    for (int n = 0; n < NSLOT; n++) {
        const float* xg_n = p_xg + (size_t)n * BB * G4;
        launch_sgemm(BB, G4, HH, p_h, HH, lstm_Whh, HH, 1,
                     p_gates, G4, nullptr, xg_n);
        step_pointwise_kernel<<<(BB * HH + 255) / 256, 256>>>();
    }

    // 6) outer LSTM: gates = x@Wih_x.T + b_ih + h_mem@Wih_h.T + h_lstm@W_hh.T
    launch_sgemm(BB, G4, DD, x_t, DD, W_ih, DD + HH, 1, p_gates, G4, b_ih, nullptr);
    launch_sgemm(BB, G4, HH, p_h, HH, W_ih + DD, DD + HH, 1, p_gates, G4, nullptr, p_gates);
    launch_sgemm(BB, G4, HH, h_lstm, HH, W_hh, HH, 1, p_gates, G4, nullptr, p_gates);
    outer_pointwise_kernel<<<(BB * HH + 255) / 256, 256>>>(c_lstm, out);
}

// round 4
// speedup vs baseline: 7.6852x; 7.6852x over previous
#include <cuda_runtime.h>
#include <math.h>
#include <stdint.h>

#define BB    2048
#define DD    256
#define HH    512
#define NSLOT 64
#define FEAT  513
#define FEATP 544
#define G4    2048

#define OFF_H      ((size_t)0)
#define OFF_C      ((size_t)1048576)
#define OFF_HMEM   ((size_t)2097152)
#define OFF_SLOTS  ((size_t)3145728)
#define OFF_CUM    ((size_t)36700160)
#define OFF_DELTA  ((size_t)70254592)
#define OFF_FILLED ((size_t)70385664)

// ------------------------------- scratch ------------------------------------
__device__ float g_q[BB * HH];
__device__ float g_kq[BB * DD];
__device__ float g_v[BB * DD];
__device__ int   g_idx[BB];
__device__ float g_bias[G4];
__device__ float g_wihp[(size_t)G4 * FEATP];
__device__ float g_mem[(size_t)NSLOT * BB * FEATP];
__device__ float g_xg[(size_t)NSLOT * BB * G4];
__device__ float g_gates[(size_t)BB * G4];
__device__ float g_h[BB * HH];
__device__ float g_c[BB * HH];
__device__ int   g_fmode;

__device__ __forceinline__ float sigf(float x) { return 1.0f / (1.0f + expf(-x)); }

__device__ __forceinline__ int read_filled(const void* p, size_t i, int m) {
    if (m == 0) return ((const float*)p)[i] != 0.0f;
    if (m == 1) return ((const int*)p)[i] != 0;
    if (m == 2) return ((const unsigned char*)p)[i] != 0;
    return ((const unsigned short*)p)[i] != 0;
}

// ----------------------------- PTX helpers ----------------------------------
__device__ __forceinline__ uint32_t smem_u32(const void* p) {
    uint32_t a;
    asm("{ .reg .u64 t; cvta.to.shared.u64 t, %1; cvt.u32.u64 %0, t; }" : "=r"(a) : "l"(p));
    return a;
}
__device__ __forceinline__ void cpasync16(uint32_t dst, const void* src) {
    asm volatile("cp.async.cg.shared.global [%0], [%1], 16;\n" :: "r"(dst), "l"(src));
}
#define CP_COMMIT() asm volatile("cp.async.commit_group;\n" ::: "memory")
#define CP_WAIT1()  asm volatile("cp.async.wait_group 1;\n" ::: "memory")
#define CP_WAIT0()  asm volatile("cp.async.wait_group 0;\n" ::: "memory")

__device__ __forceinline__ uint32_t f2tf(float x) {
    uint32_t r;
    asm("cvt.rna.tf32.f32 %0, %1;" : "=r"(r) : "f"(x));
    return r;
}
__device__ __forceinline__ void mma8(float* c, const uint32_t* A, const uint32_t* B) {
    asm volatile(
        "mma.sync.aligned.m16n8k8.row.col.f32.tf32.tf32.f32 "
        "{%0,%1,%2,%3}, {%4,%5,%6,%7}, {%8,%9}, {%0,%1,%2,%3};"
        : "+f"(c[0]), "+f"(c[1]), "+f"(c[2]), "+f"(c[3])
        : "r"(A[0]), "r"(A[1]), "r"(A[2]), "r"(A[3]), "r"(B[0]), "r"(B[1]));
}

// ------------------------- tf32 warp-MMA GEMM -------------------------------
// C[M,N] = A[M,K] @ W[N,K]^T (+bias[n]) (+Cin[m,n]).  M,N mult of 128, K mult of 32.
#define PADK 36
#define TILE_FLOATS 4608                 // 128 * PADK
#define BUF_FLOATS  9216                 // A + B
#define SMEM_DYN    (2 * BUF_FLOATS * 4) // 73728 bytes

struct GArgs {
    int K, lda, ldw, ldc;
    const float *A, *W, *bias, *Cin;
    float *C;
};

__device__ __forceinline__ void load_stage(uint32_t smb, const GArgs& a,
                                           int bm, int bn, int k0, int tid, int buf) {
    const uint32_t base = smb + (uint32_t)buf * BUF_FLOATS * 4;
#pragma unroll
    for (int i = 0; i < 4; i++) {
        int idx = tid + i * 256;
        int r = idx >> 3, c = idx & 7;
        cpasync16(base + (uint32_t)(r * PADK + c * 4) * 4,
                  a.A + (size_t)(bm + r) * a.lda + k0 + c * 4);
    }
#pragma unroll
    for (int i = 0; i < 4; i++) {
        int idx = tid + i * 256;
        int r = idx >> 3, c = idx & 7;
        cpasync16(base + TILE_FLOATS * 4 + (uint32_t)(r * PADK + c * 4) * 4,
                  a.W + (size_t)(bn + r) * a.ldw + k0 + c * 4);
    }
}

__global__ void __launch_bounds__(256) mma_gemm_kernel(const GArgs a) {
    extern __shared__ float sm[];
    const uint32_t smb = smem_u32(sm);

    const int tid = threadIdx.x;
    const int wid = tid >> 5, lane = tid & 31;
    const int wm = wid & 3, wn = wid >> 2;      // 4 x 2 warp grid
    const int gid = lane >> 2, tg = lane & 3;
    const int bm = blockIdx.y * 128;
    const int bn = blockIdx.x * 128;

    float acc[2][8][4];
#pragma unroll
    for (int mt = 0; mt < 2; mt++)
#pragma unroll
        for (int nt = 0; nt < 8; nt++)
#pragma unroll
            for (int e = 0; e < 4; e++) acc[mt][nt][e] = 0.0f;

    const int KT = a.K >> 5;
    load_stage(smb, a, bm, bn, 0, tid, 0);
    CP_COMMIT();

    for (int kt = 0; kt < KT; kt++) {
        const int cur = kt & 1;
        if (kt + 1 < KT) {
            load_stage(smb, a, bm, bn, (kt + 1) * 32, tid, cur ^ 1);
            CP_COMMIT();
            CP_WAIT1();
        } else {
            CP_WAIT0();
        }
        __syncthreads();

        const float* As = sm + cur * BUF_FLOATS;
        const float* Bs = As + TILE_FLOATS;
#pragma unroll
        for (int k8 = 0; k8 < 4; k8++) {
            const int kb = k8 * 8;
            uint32_t af[2][4];
#pragma unroll
            for (int mt = 0; mt < 2; mt++) {
                int r0 = wm * 32 + mt * 16 + gid;
                af[mt][0] = f2tf(As[r0 * PADK + kb + tg]);
                af[mt][1] = f2tf(As[(r0 + 8) * PADK + kb + tg]);
                af[mt][2] = f2tf(As[r0 * PADK + kb + tg + 4]);
                af[mt][3] = f2tf(As[(r0 + 8) * PADK + kb + tg + 4]);
            }
            uint32_t bf[8][2];
#pragma unroll
            for (int nt = 0; nt < 8; nt++) {
                int n0 = wn * 64 + nt * 8 + gid;
                bf[nt][0] = f2tf(Bs[n0 * PADK + kb + tg]);
                bf[nt][1] = f2tf(Bs[n0 * PADK + kb + tg + 4]);
            }
#pragma unroll
            for (int mt = 0; mt < 2; mt++)
#pragma unroll
                for (int nt = 0; nt < 8; nt++)
                    mma8(acc[mt][nt], af[mt], bf[nt]);
        }
        __syncthreads();
    }

    // epilogue
#pragma unroll
    for (int mt = 0; mt < 2; mt++) {
        const size_t r0 = (size_t)bm + wm * 32 + mt * 16 + gid;
        const size_t r1 = r0 + 8;
#pragma unroll
        for (int nt = 0; nt < 8; nt++) {
            const int col = bn + wn * 64 + nt * 8 + tg * 2;
            float2 v0 = make_float2(acc[mt][nt][0], acc[mt][nt][1]);
            float2 v1 = make_float2(acc[mt][nt][2], acc[mt][nt][3]);
            if (a.bias) {
                float2 b2 = *(const float2*)(a.bias + col);
                v0.x += b2.x; v0.y += b2.y;
                v1.x += b2.x; v1.y += b2.y;
            }
            if (a.Cin) {
                float2 c0 = *(const float2*)(a.Cin + r0 * a.ldc + col);
                float2 c1 = *(const float2*)(a.Cin + r1 * a.ldc + col);
                v0.x += c0.x; v0.y += c0.y;
                v1.x += c1.x; v1.y += c1.y;
            }
            *(float2*)(a.C + r0 * a.ldc + col) = v0;
            *(float2*)(a.C + r1 * a.ldc + col) = v1;
        }
    }
}

static void launch_tc(int M, int N, int K, const float* A, int lda,
                      const float* W, int ldw, float* C, int ldc,
                      const float* bias, const float* Cin) {
    static int attr_set = 0;
    if (!attr_set) {
        cudaFuncSetAttribute(mma_gemm_kernel,
                             cudaFuncAttributeMaxDynamicSharedMemorySize, SMEM_DYN);
        attr_set = 1;
    }
    GArgs a; a.K = K; a.lda = lda; a.ldw = ldw; a.ldc = ldc;
    a.A = A; a.W = W; a.bias = bias; a.Cin = Cin; a.C = C;
    dim3 grid(N / 128, M / 128);
    mma_gemm_kernel<<<grid, 256, SMEM_DYN>>>(a);
}

// --------------------------- misc kernels (fp32 path) ------------------------
__global__ void detect_filled_kernel(const unsigned int* __restrict__ w) {
    __shared__ int flags[3];
    if (threadIdx.x < 3) flags[threadIdx.x] = 0;
    __syncthreads();
    for (int i = threadIdx.x; i < (BB * NSLOT) / 4; i += blockDim.x) {
        unsigned v = w[i];
        if (v == 0x3F800000u)      atomicOr(&flags[0], 1);
        else if (v == 0x3F803F80u) atomicOr(&flags[1], 1);
        else if (v > 1u)           atomicOr(&flags[2], 1);
    }
    __syncthreads();
    if (threadIdx.x == 0) {
        int m;
        if (flags[1])      m = 3;
        else if (flags[0]) m = 0;
        else if (flags[2]) m = 2;
        else               m = 1;
        g_fmode = m;
    }
}

__global__ void zero_hc_kernel() {
    int e = blockIdx.x * blockDim.x + threadIdx.x;
    if (e < BB * HH) { g_h[e] = 0.0f; g_c[e] = 0.0f; }
}

__global__ void combine_bias_kernel(const float* __restrict__ bih,
                                    const float* __restrict__ bhh) {
    int e = blockIdx.x * blockDim.x + threadIdx.x;
    if (e < G4) g_bias[e] = bih[e] + bhh[e];
}

__global__ void pad_wih_kernel(const float* __restrict__ w) {
    int e = blockIdx.x * blockDim.x + threadIdx.x;
    if (e >= G4 * FEATP) return;
    int r = e / FEATP, k = e % FEATP;
    g_wihp[e] = (k < FEAT) ? w[(size_t)r * FEAT + k] : 0.0f;
}

// fp32 SGEMM for the small, argmax-sensitive q/kq/v GEMMs
__global__ void __launch_bounds__(256)
sgemm_kernel(int M, int N, int K,
             const float* __restrict__ A, int lda,
             const float* __restrict__ W, int ldw, int wTrans,
             float* __restrict__ C, int ldc, const float* __restrict__ bias) {
    __shared__ __align__(16) float As[16][128];
    __shared__ __align__(16) float Ws[16][128];
    const int tid = threadIdx.x;
    const int tx = tid & 15, ty = tid >> 4;
    const int bm = blockIdx.y * 128, bn = blockIdx.x * 128;
    float acc[8][8];
#pragma unroll
    for (int i = 0; i < 8; i++)
#pragma unroll
        for (int j = 0; j < 8; j++) acc[i][j] = 0.0f;
    for (int k0 = 0; k0 < K; k0 += 16) {
#pragma unroll
        for (int l = tid; l < 2048; l += 256) {
            int m = l >> 4, k = l & 15;
            int gm = bm + m, gk = k0 + k;
            As[k][m] = (gm < M && gk < K) ? A[(size_t)gm * lda + gk] : 0.0f;
        }
#pragma unroll
        for (int l = tid; l < 2048; l += 256) {
            int n = l >> 4, k = l & 15;
            int gn = bn + n, gk = k0 + k;
            float v = 0.0f;
            if (gn < N && gk < K)
                v = wTrans ? W[(size_t)gn * ldw + gk] : W[(size_t)gk * ldw + gn];
            Ws[k][n] = v;
        }
        __syncthreads();
#pragma unroll
        for (int k = 0; k < 16; k++) {
            float4 a0 = *(const float4*)&As[k][ty * 8];
            float4 a1 = *(const float4*)&As[k][ty * 8 + 4];
            float4 w0 = *(const float4*)&Ws[k][tx * 8];
            float4 w1 = *(const float4*)&Ws[k][tx * 8 + 4];
            float aa[8] = {a0.x, a0.y, a0.z, a0.w, a1.x, a1.y, a1.z, a1.w};
            float ww[8] = {w0.x, w0.y, w0.z, w0.w, w1.x, w1.y, w1.z, w1.w};
#pragma unroll
            for (int i = 0; i < 8; i++)
#pragma unroll
                for (int j = 0; j < 8; j++) acc[i][j] = fmaf(aa[i], ww[j], acc[i][j]);
        }
        __syncthreads();
    }
#pragma unroll
    for (int i = 0; i < 8; i++) {
        int gm = bm + ty * 8 + i;
        if (gm >= M) continue;
#pragma unroll
        for (int j = 0; j < 8; j++) {
            int gn = bn + tx * 8 + j;
            if (gn >= N) continue;
            float v = acc[i][j];
            if (bias) v += bias[gn];
            C[(size_t)gm * ldc + gn] = v;
        }
    }
}

__global__ void select_idx_kernel(const float* __restrict__ slots,
                                  const void* __restrict__ filled) {
    const int b = blockIdx.x;
    const int t = threadIdx.x;
    __shared__ float kq_s[DD];
    __shared__ float sims[NSLOT];
    __shared__ int   emp[NSLOT];
    for (int d = t; d < DD; d += NSLOT) kq_s[d] = g_kq[b * DD + d];
    __syncthreads();
    const float* sp = slots + ((size_t)b * NSLOT + t) * DD;
    float s = 0.0f;
    for (int d = 0; d < DD; d++) s = fmaf(sp[d], kq_s[d], s);
    sims[t] = s;
    emp[t]  = !read_filled(filled, (size_t)b * NSLOT + t, g_fmode);
    __syncthreads();
    if (t == 0) {
        int idx = -1;
        for (int n = 0; n < NSLOT; n++) if (emp[n]) { idx = n; break; }
        if (idx < 0) {
            float best = sims[0]; idx = 0;
            for (int n = 1; n < NSLOT; n++) if (sims[n] > best) { best = sims[n]; idx = n; }
        }
        g_idx[b] = idx;
    }
}

__global__ void update_write_kernel(const float* __restrict__ slots,
                                    const float* __restrict__ cum,
                                    const float* __restrict__ delta,
                                    const void* __restrict__ filled,
                                    const float* __restrict__ x,
                                    float* __restrict__ out) {
    size_t e = (size_t)blockIdx.x * blockDim.x + threadIdx.x;
    if (e >= (size_t)BB * NSLOT * DD) return;
    int d = (int)(e % DD);
    size_t bn = e / DD;
    int n = (int)(bn % NSLOT);
    int b = (int)(bn / NSLOT);
    int idx = g_idx[b];

    float xv = x[b * DD + d];
    float sl = slots[e];
    float cf = cum[e] + xv;
    if (n == idx) { sl = g_v[b * DD + d]; cf = xv; }

    out[OFF_SLOTS + e] = sl;
    out[OFF_CUM + e]   = cf;

    size_t mbase = ((size_t)n * BB + b) * FEATP;
    g_mem[mbase + d]      = sl;
    g_mem[mbase + DD + d] = cf;
    if (d < FEATP - FEAT) g_mem[mbase + FEAT + d] = 0.0f;
    if (d == 0) {
        float dt = (n == idx) ? 0.0f : delta[bn] + 1.0f;
        out[OFF_DELTA + bn] = dt;
        g_mem[mbase + 2 * DD] = dt;
        int fl = (n == idx) ? 1 : read_filled(filled, bn, g_fmode);
        out[OFF_FILLED + bn] = fl ? 1.0f : 0.0f;
    }
}

__global__ void step_pointwise_kernel() {
    int e = blockIdx.x * blockDim.x + threadIdx.x;
    if (e >= BB * HH) return;
    int b = e / HH, j = e % HH;
    size_t base = (size_t)b * G4 + j;
    float i = sigf(g_gates[base]);
    float f = sigf(g_gates[base + HH]);
    float g = tanhf(g_gates[base + 2 * HH]);
    float o = sigf(g_gates[base + 3 * HH]);
    float c = f * g_c[e] + i * g;
    g_c[e] = c;
    g_h[e] = o * tanhf(c);
}

__global__ void outer_pointwise_kernel(const float* __restrict__ c_in,
                                       float* __restrict__ out) {
    int e = blockIdx.x * blockDim.x + threadIdx.x;
    if (e >= BB * HH) return;
    int b = e / HH, j = e % HH;
    size_t base = (size_t)b * G4 + j;
    float i = sigf(g_gates[base]);
    float f = sigf(g_gates[base + HH]);
    float g = tanhf(g_gates[base + 2 * HH]);
    float o = sigf(g_gates[base + 3 * HH]);
    float c = f * c_in[e] + i * g;
    out[OFF_C + e] = c;
    out[OFF_H + e] = o * tanhf(c);
    out[OFF_HMEM + e] = g_h[e];
}

// --------------------------------- launch -----------------------------------
extern "C" void kernel_launch(void* const* d_in, const int* in_sizes, int n_in,
                              void* d_out, int out_size) {
    const float* x_t      = (const float*)d_in[0];
    const float* h_lstm   = (const float*)d_in[1];
    const float* c_lstm   = (const float*)d_in[2];
    const float* slots    = (const float*)d_in[4];
    const float* cum      = (const float*)d_in[5];
    const float* delta    = (const float*)d_in[6];
    const void*  filled   = (const void*)d_in[7];
    const float* Wq       = (const float*)d_in[8];
    const float* Wk       = (const float*)d_in[9];
    const float* Wv       = (const float*)d_in[10];
    const float* bv       = (const float*)d_in[11];
    const float* lstm_Wih = (const float*)d_in[12];
    const float* lstm_Whh = (const float*)d_in[13];
    const float* lstm_bih = (const float*)d_in[14];
    const float* lstm_bhh = (const float*)d_in[15];
    const float* W_ih     = (const float*)d_in[16];
    const float* b_ih     = (const float*)d_in[17];
    const float* W_hh     = (const float*)d_in[18];
    float* out = (float*)d_out;

    float *p_q, *p_kq, *p_v, *p_mem, *p_xg, *p_gates, *p_h, *p_bias, *p_wihp;
    cudaGetSymbolAddress((void**)&p_q, g_q);
    cudaGetSymbolAddress((void**)&p_kq, g_kq);
    cudaGetSymbolAddress((void**)&p_v, g_v);
    cudaGetSymbolAddress((void**)&p_mem, g_mem);
    cudaGetSymbolAddress((void**)&p_xg, g_xg);
    cudaGetSymbolAddress((void**)&p_gates, g_gates);
    cudaGetSymbolAddress((void**)&p_h, g_h);
    cudaGetSymbolAddress((void**)&p_bias, g_bias);
    cudaGetSymbolAddress((void**)&p_wihp, g_wihp);

    detect_filled_kernel<<<1, 256>>>((const unsigned int*)filled);
    zero_hc_kernel<<<(BB * HH + 255) / 256, 256>>>();
    combine_bias_kernel<<<(G4 + 255) / 256, 256>>>(lstm_bih, lstm_bhh);
    pad_wih_kernel<<<(G4 * FEATP + 255) / 256, 256>>>(lstm_Wih);

    // q/kq/v in fp32 (argmax-sensitive)
    {
        dim3 g1(HH / 128, BB / 128);
        sgemm_kernel<<<g1, 256>>>(BB, HH, DD, x_t, DD, Wq, DD, 1, p_q, HH, nullptr);
        dim3 g2(DD / 128, BB / 128);
        sgemm_kernel<<<g2, 256>>>(BB, DD, HH, p_q, HH, Wk, DD, 0, p_kq, DD, nullptr);
        sgemm_kernel<<<g2, 256>>>(BB, DD, DD, x_t, DD, Wv, DD, 1, p_v, DD, bv);
    }

    select_idx_kernel<<<BB, NSLOT>>>(slots, filled);
    {
        size_t tot = (size_t)BB * NSLOT * DD;
        update_write_kernel<<<(unsigned)((tot + 255) / 256), 256>>>(
            slots, cum, delta, filled, x_t, out);
    }

    // xg = mem_seq @ WihP.T + (bih+bhh)    (tf32 warp MMA)
    launch_tc(NSLOT * BB, G4, FEATP, p_mem, FEATP, p_wihp, FEATP,
              p_xg, G4, p_bias, nullptr);

    // slot-LSTM recurrence
    for (int n = 0; n < NSLOT; n++) {
        const float* xg_n = p_xg + (size_t)n * BB * G4;
        launch_tc(BB, G4, HH, p_h, HH, lstm_Whh, HH, p_gates, G4, nullptr, xg_n);
        step_pointwise_kernel<<<(BB * HH + 255) / 256, 256>>>();
    }

    // outer LSTM
    launch_tc(BB, G4, DD, x_t, DD, W_ih, DD + HH, p_gates, G4, b_ih, nullptr);
    launch_tc(BB, G4, HH, p_h, HH, W_ih + DD, DD + HH, p_gates, G4, nullptr, p_gates);
    launch_tc(BB, G4, HH, h_lstm, HH, W_hh, HH, p_gates, G4, nullptr, p_gates);
    outer_pointwise_kernel<<<(BB * HH + 255) / 256, 256>>>(c_lstm, out);
}

// round 5
// speedup vs baseline: 7.6930x; 1.0010x over previous
#include <cuda_runtime.h>
#include <math.h>
#include <stdint.h>

#define BB    2048
#define DD    256
#define HH    512
#define NSLOT 64
#define FEAT  513
#define FEATP 544
#define G4    2048

#define OFF_H      ((size_t)0)
#define OFF_C      ((size_t)1048576)
#define OFF_HMEM   ((size_t)2097152)
#define OFF_SLOTS  ((size_t)3145728)
#define OFF_CUM    ((size_t)36700160)
#define OFF_DELTA  ((size_t)70254592)
#define OFF_FILLED ((size_t)70385664)

// ------------------------------- scratch ------------------------------------
__device__ float g_q[BB * HH];
__device__ float g_kq[BB * DD];
__device__ float g_v[BB * DD];
__device__ int   g_idx[BB];
__device__ float g_bias[G4];
__device__ float g_wihp[(size_t)G4 * FEATP];
__device__ float g_mem[(size_t)NSLOT * BB * FEATP];
__device__ float g_xg[(size_t)NSLOT * BB * G4];
__device__ float g_gates[(size_t)BB * G4];
__device__ float g_h[BB * HH];
__device__ float g_c[BB * HH];
__device__ int   g_fmode;

__device__ __forceinline__ float sigf(float x) { return 1.0f / (1.0f + expf(-x)); }

__device__ __forceinline__ int read_filled(const void* p, size_t i, int m) {
    if (m == 0) return ((const float*)p)[i] != 0.0f;
    if (m == 1) return ((const int*)p)[i] != 0;
    if (m == 2) return ((const unsigned char*)p)[i] != 0;
    return ((const unsigned short*)p)[i] != 0;
}

// ----------------------------- PTX helpers ----------------------------------
__device__ __forceinline__ uint32_t smem_u32(const void* p) {
    uint32_t a;
    asm("{ .reg .u64 t; cvta.to.shared.u64 t, %1; cvt.u32.u64 %0, t; }" : "=r"(a) : "l"(p));
    return a;
}
__device__ __forceinline__ void cpasync16(uint32_t dst, const void* src) {
    asm volatile("cp.async.cg.shared.global [%0], [%1], 16;\n" :: "r"(dst), "l"(src));
}
#define CP_COMMIT() asm volatile("cp.async.commit_group;\n" ::: "memory")
#define CP_WAIT1()  asm volatile("cp.async.wait_group 1;\n" ::: "memory")
#define CP_WAIT0()  asm volatile("cp.async.wait_group 0;\n" ::: "memory")

__device__ __forceinline__ uint32_t f2tf(float x) {
    uint32_t r;
    asm("cvt.rna.tf32.f32 %0, %1;" : "=r"(r) : "f"(x));
    return r;
}
__device__ __forceinline__ void mma8(float* c, const uint32_t* A, const uint32_t* B) {
    asm volatile(
        "mma.sync.aligned.m16n8k8.row.col.f32.tf32.tf32.f32 "
        "{%0,%1,%2,%3}, {%4,%5,%6,%7}, {%8,%9}, {%0,%1,%2,%3};"
        : "+f"(c[0]), "+f"(c[1]), "+f"(c[2]), "+f"(c[3])
        : "r"(A[0]), "r"(A[1]), "r"(A[2]), "r"(A[3]), "r"(B[0]), "r"(B[1]));
}

// ------------------------- tf32 warp-MMA GEMM -------------------------------
// C[M,N] = A[M,K] @ W[N,K]^T (+bias[n]) (+Cin[m,n]).  M,N mult of 128, K mult of 32.
#define PADK 36
#define TILE_FLOATS 4608                 // 128 * PADK
#define BUF_FLOATS  9216                 // A + B
#define SMEM_DYN    (2 * BUF_FLOATS * 4) // 73728 bytes

struct GArgs {
    int K, lda, ldw, ldc;
    const float *A, *W, *bias, *Cin;
    float *C;
};

__device__ __forceinline__ void load_stage(uint32_t smb, const GArgs& a,
                                           int bm, int bn, int k0, int tid, int buf) {
    const uint32_t base = smb + (uint32_t)buf * BUF_FLOATS * 4;
#pragma unroll
    for (int i = 0; i < 4; i++) {
        int idx = tid + i * 256;
        int r = idx >> 3, c = idx & 7;
        cpasync16(base + (uint32_t)(r * PADK + c * 4) * 4,
                  a.A + (size_t)(bm + r) * a.lda + k0 + c * 4);
    }
#pragma unroll
    for (int i = 0; i < 4; i++) {
        int idx = tid + i * 256;
        int r = idx >> 3, c = idx & 7;
        cpasync16(base + TILE_FLOATS * 4 + (uint32_t)(r * PADK + c * 4) * 4,
                  a.W + (size_t)(bn + r) * a.ldw + k0 + c * 4);
    }
}

__global__ void __launch_bounds__(256) mma_gemm_kernel(const GArgs a) {
    extern __shared__ float sm[];
    const uint32_t smb = smem_u32(sm);

    const int tid = threadIdx.x;
    const int wid = tid >> 5, lane = tid & 31;
    const int wm = wid & 3, wn = wid >> 2;      // 4 x 2 warp grid
    const int gid = lane >> 2, tg = lane & 3;
    const int bm = blockIdx.y * 128;
    const int bn = blockIdx.x * 128;

    float acc[2][8][4];
#pragma unroll
    for (int mt = 0; mt < 2; mt++)
#pragma unroll
        for (int nt = 0; nt < 8; nt++)
#pragma unroll
            for (int e = 0; e < 4; e++) acc[mt][nt][e] = 0.0f;

    const int KT = a.K >> 5;
    load_stage(smb, a, bm, bn, 0, tid, 0);
    CP_COMMIT();

    for (int kt = 0; kt < KT; kt++) {
        const int cur = kt & 1;
        if (kt + 1 < KT) {
            load_stage(smb, a, bm, bn, (kt + 1) * 32, tid, cur ^ 1);
            CP_COMMIT();
            CP_WAIT1();
        } else {
            CP_WAIT0();
        }
        __syncthreads();

        const float* As = sm + cur * BUF_FLOATS;
        const float* Bs = As + TILE_FLOATS;
#pragma unroll
        for (int k8 = 0; k8 < 4; k8++) {
            const int kb = k8 * 8;
            uint32_t af[2][4];
#pragma unroll
            for (int mt = 0; mt < 2; mt++) {
                int r0 = wm * 32 + mt * 16 + gid;
                af[mt][0] = f2tf(As[r0 * PADK + kb + tg]);
                af[mt][1] = f2tf(As[(r0 + 8) * PADK + kb + tg]);
                af[mt][2] = f2tf(As[r0 * PADK + kb + tg + 4]);
                af[mt][3] = f2tf(As[(r0 + 8) * PADK + kb + tg + 4]);
            }
            uint32_t bf[8][2];
#pragma unroll
            for (int nt = 0; nt < 8; nt++) {
                int n0 = wn * 64 + nt * 8 + gid;
                bf[nt][0] = f2tf(Bs[n0 * PADK + kb + tg]);
                bf[nt][1] = f2tf(Bs[n0 * PADK + kb + tg + 4]);
            }
#pragma unroll
            for (int mt = 0; mt < 2; mt++)
#pragma unroll
                for (int nt = 0; nt < 8; nt++)
                    mma8(acc[mt][nt], af[mt], bf[nt]);
        }
        __syncthreads();
    }

    // epilogue
#pragma unroll
    for (int mt = 0; mt < 2; mt++) {
        const size_t r0 = (size_t)bm + wm * 32 + mt * 16 + gid;
        const size_t r1 = r0 + 8;
#pragma unroll
        for (int nt = 0; nt < 8; nt++) {
            const int col = bn + wn * 64 + nt * 8 + tg * 2;
            float2 v0 = make_float2(acc[mt][nt][0], acc[mt][nt][1]);
            float2 v1 = make_float2(acc[mt][nt][2], acc[mt][nt][3]);
            if (a.bias) {
                float2 b2 = *(const float2*)(a.bias + col);
                v0.x += b2.x; v0.y += b2.y;
                v1.x += b2.x; v1.y += b2.y;
            }
            if (a.Cin) {
                float2 c0 = *(const float2*)(a.Cin + r0 * a.ldc + col);
                float2 c1 = *(const float2*)(a.Cin + r1 * a.ldc + col);
                v0.x += c0.x; v0.y += c0.y;
                v1.x += c1.x; v1.y += c1.y;
            }
            *(float2*)(a.C + r0 * a.ldc + col) = v0;
            *(float2*)(a.C + r1 * a.ldc + col) = v1;
        }
    }
}

static void launch_tc(int M, int N, int K, const float* A, int lda,
                      const float* W, int ldw, float* C, int ldc,
                      const float* bias, const float* Cin) {
    static int attr_set = 0;
    if (!attr_set) {
        cudaFuncSetAttribute(mma_gemm_kernel,
                             cudaFuncAttributeMaxDynamicSharedMemorySize, SMEM_DYN);
        attr_set = 1;
    }
    GArgs a; a.K = K; a.lda = lda; a.ldw = ldw; a.ldc = ldc;
    a.A = A; a.W = W; a.bias = bias; a.Cin = Cin; a.C = C;
    dim3 grid(N / 128, M / 128);
    mma_gemm_kernel<<<grid, 256, SMEM_DYN>>>(a);
}

// --------------------------- misc kernels (fp32 path) ------------------------
__global__ void detect_filled_kernel(const unsigned int* __restrict__ w) {
    __shared__ int flags[3];
    if (threadIdx.x < 3) flags[threadIdx.x] = 0;
    __syncthreads();
    for (int i = threadIdx.x; i < (BB * NSLOT) / 4; i += blockDim.x) {
        unsigned v = w[i];
        if (v == 0x3F800000u)      atomicOr(&flags[0], 1);
        else if (v == 0x3F803F80u) atomicOr(&flags[1], 1);
        else if (v > 1u)           atomicOr(&flags[2], 1);
    }
    __syncthreads();
    if (threadIdx.x == 0) {
        int m;
        if (flags[1])      m = 3;
        else if (flags[0]) m = 0;
        else if (flags[2]) m = 2;
        else               m = 1;
        g_fmode = m;
    }
}

__global__ void zero_hc_kernel() {
    int e = blockIdx.x * blockDim.x + threadIdx.x;
    if (e < BB * HH) { g_h[e] = 0.0f; g_c[e] = 0.0f; }
}

__global__ void combine_bias_kernel(const float* __restrict__ bih,
                                    const float* __restrict__ bhh) {
    int e = blockIdx.x * blockDim.x + threadIdx.x;
    if (e < G4) g_bias[e] = bih[e] + bhh[e];
}

__global__ void pad_wih_kernel(const float* __restrict__ w) {
    int e = blockIdx.x * blockDim.x + threadIdx.x;
    if (e >= G4 * FEATP) return;
    int r = e / FEATP, k = e % FEATP;
    g_wihp[e] = (k < FEAT) ? w[(size_t)r * FEAT + k] : 0.0f;
}

// fp32 SGEMM for the small, argmax-sensitive q/kq/v GEMMs
__global__ void __launch_bounds__(256)
sgemm_kernel(int M, int N, int K,
             const float* __restrict__ A, int lda,
             const float* __restrict__ W, int ldw, int wTrans,
             float* __restrict__ C, int ldc, const float* __restrict__ bias) {
    __shared__ __align__(16) float As[16][128];
    __shared__ __align__(16) float Ws[16][128];
    const int tid = threadIdx.x;
    const int tx = tid & 15, ty = tid >> 4;
    const int bm = blockIdx.y * 128, bn = blockIdx.x * 128;
    float acc[8][8];
#pragma unroll
    for (int i = 0; i < 8; i++)
#pragma unroll
        for (int j = 0; j < 8; j++) acc[i][j] = 0.0f;
    for (int k0 = 0; k0 < K; k0 += 16) {
#pragma unroll
        for (int l = tid; l < 2048; l += 256) {
            int m = l >> 4, k = l & 15;
            int gm = bm + m, gk = k0 + k;
            As[k][m] = (gm < M && gk < K) ? A[(size_t)gm * lda + gk] : 0.0f;
        }
#pragma unroll
        for (int l = tid; l < 2048; l += 256) {
            int n = l >> 4, k = l & 15;
            int gn = bn + n, gk = k0 + k;
            float v = 0.0f;
            if (gn < N && gk < K)
                v = wTrans ? W[(size_t)gn * ldw + gk] : W[(size_t)gk * ldw + gn];
            Ws[k][n] = v;
        }
        __syncthreads();
#pragma unroll
        for (int k = 0; k < 16; k++) {
            float4 a0 = *(const float4*)&As[k][ty * 8];
            float4 a1 = *(const float4*)&As[k][ty * 8 + 4];
            float4 w0 = *(const float4*)&Ws[k][tx * 8];
            float4 w1 = *(const float4*)&Ws[k][tx * 8 + 4];
            float aa[8] = {a0.x, a0.y, a0.z, a0.w, a1.x, a1.y, a1.z, a1.w};
            float ww[8] = {w0.x, w0.y, w0.z, w0.w, w1.x, w1.y, w1.z, w1.w};
#pragma unroll
            for (int i = 0; i < 8; i++)
#pragma unroll
                for (int j = 0; j < 8; j++) acc[i][j] = fmaf(aa[i], ww[j], acc[i][j]);
        }
        __syncthreads();
    }
#pragma unroll
    for (int i = 0; i < 8; i++) {
        int gm = bm + ty * 8 + i;
        if (gm >= M) continue;
#pragma unroll
        for (int j = 0; j < 8; j++) {
            int gn = bn + tx * 8 + j;
            if (gn >= N) continue;
            float v = acc[i][j];
            if (bias) v += bias[gn];
            C[(size_t)gm * ldc + gn] = v;
        }
    }
}

__global__ void select_idx_kernel(const float* __restrict__ slots,
                                  const void* __restrict__ filled) {
    const int b = blockIdx.x;
    const int t = threadIdx.x;
    __shared__ float kq_s[DD];
    __shared__ float sims[NSLOT];
    __shared__ int   emp[NSLOT];
    for (int d = t; d < DD; d += NSLOT) kq_s[d] = g_kq[b * DD + d];
    __syncthreads();
    const float* sp = slots + ((size_t)b * NSLOT + t) * DD;
    float s = 0.0f;
    for (int d = 0; d < DD; d++) s = fmaf(sp[d], kq_s[d], s);
    sims[t] = s;
    emp[t]  = !read_filled(filled, (size_t)b * NSLOT + t, g_fmode);
    __syncthreads();
    if (t == 0) {
        int idx = -1;
        for (int n = 0; n < NSLOT; n++) if (emp[n]) { idx = n; break; }
        if (idx < 0) {
            float best = sims[0]; idx = 0;
            for (int n = 1; n < NSLOT; n++) if (sims[n] > best) { best = sims[n]; idx = n; }
        }
        g_idx[b] = idx;
    }
}

__global__ void update_write_kernel(const float* __restrict__ slots,
                                    const float* __restrict__ cum,
                                    const float* __restrict__ delta,
                                    const void* __restrict__ filled,
                                    const float* __restrict__ x,
                                    float* __restrict__ out) {
    size_t e = (size_t)blockIdx.x * blockDim.x + threadIdx.x;
    if (e >= (size_t)BB * NSLOT * DD) return;
    int d = (int)(e % DD);
    size_t bn = e / DD;
    int n = (int)(bn % NSLOT);
    int b = (int)(bn / NSLOT);
    int idx = g_idx[b];

    float xv = x[b * DD + d];
    float sl = slots[e];
    float cf = cum[e] + xv;
    if (n == idx) { sl = g_v[b * DD + d]; cf = xv; }

    out[OFF_SLOTS + e] = sl;
    out[OFF_CUM + e]   = cf;

    size_t mbase = ((size_t)n * BB + b) * FEATP;
    g_mem[mbase + d]      = sl;
    g_mem[mbase + DD + d] = cf;
    if (d < FEATP - FEAT) g_mem[mbase + FEAT + d] = 0.0f;
    if (d == 0) {
        float dt = (n == idx) ? 0.0f : delta[bn] + 1.0f;
        out[OFF_DELTA + bn] = dt;
        g_mem[mbase + 2 * DD] = dt;
        int fl = (n == idx) ? 1 : read_filled(filled, bn, g_fmode);
        out[OFF_FILLED + bn] = fl ? 1.0f : 0.0f;
    }
}

__global__ void step_pointwise_kernel() {
    int e = blockIdx.x * blockDim.x + threadIdx.x;
    if (e >= BB * HH) return;
    int b = e / HH, j = e % HH;
    size_t base = (size_t)b * G4 + j;
    float i = sigf(g_gates[base]);
    float f = sigf(g_gates[base + HH]);
    float g = tanhf(g_gates[base + 2 * HH]);
    float o = sigf(g_gates[base + 3 * HH]);
    float c = f * g_c[e] + i * g;
    g_c[e] = c;
    g_h[e] = o * tanhf(c);
}

__global__ void outer_pointwise_kernel(const float* __restrict__ c_in,
                                       float* __restrict__ out) {
    int e = blockIdx.x * blockDim.x + threadIdx.x;
    if (e >= BB * HH) return;
    int b = e / HH, j = e % HH;
    size_t base = (size_t)b * G4 + j;
    float i = sigf(g_gates[base]);
    float f = sigf(g_gates[base + HH]);
    float g = tanhf(g_gates[base + 2 * HH]);
    float o = sigf(g_gates[base + 3 * HH]);
    float c = f * c_in[e] + i * g;
    out[OFF_C + e] = c;
    out[OFF_H + e] = o * tanhf(c);
    out[OFF_HMEM + e] = g_h[e];
}

// --------------------------------- launch -----------------------------------
extern "C" void kernel_launch(void* const* d_in, const int* in_sizes, int n_in,
                              void* d_out, int out_size) {
    const float* x_t      = (const float*)d_in[0];
    const float* h_lstm   = (const float*)d_in[1];
    const float* c_lstm   = (const float*)d_in[2];
    const float* slots    = (const float*)d_in[4];
    const float* cum      = (const float*)d_in[5];
    const float* delta    = (const float*)d_in[6];
    const void*  filled   = (const void*)d_in[7];
    const float* Wq       = (const float*)d_in[8];
    const float* Wk       = (const float*)d_in[9];
    const float* Wv       = (const float*)d_in[10];
    const float* bv       = (const float*)d_in[11];
    const float* lstm_Wih = (const float*)d_in[12];
    const float* lstm_Whh = (const float*)d_in[13];
    const float* lstm_bih = (const float*)d_in[14];
    const float* lstm_bhh = (const float*)d_in[15];
    const float* W_ih     = (const float*)d_in[16];
    const float* b_ih     = (const float*)d_in[17];
    const float* W_hh     = (const float*)d_in[18];
    float* out = (float*)d_out;

    float *p_q, *p_kq, *p_v, *p_mem, *p_xg, *p_gates, *p_h, *p_bias, *p_wihp;
    cudaGetSymbolAddress((void**)&p_q, g_q);
    cudaGetSymbolAddress((void**)&p_kq, g_kq);
    cudaGetSymbolAddress((void**)&p_v, g_v);
    cudaGetSymbolAddress((void**)&p_mem, g_mem);
    cudaGetSymbolAddress((void**)&p_xg, g_xg);
    cudaGetSymbolAddress((void**)&p_gates, g_gates);
    cudaGetSymbolAddress((void**)&p_h, g_h);
    cudaGetSymbolAddress((void**)&p_bias, g_bias);
    cudaGetSymbolAddress((void**)&p_wihp, g_wihp);

    detect_filled_kernel<<<1, 256>>>((const unsigned int*)filled);
    zero_hc_kernel<<<(BB * HH + 255) / 256, 256>>>();
    combine_bias_kernel<<<(G4 + 255) / 256, 256>>>(lstm_bih, lstm_bhh);
    pad_wih_kernel<<<(G4 * FEATP + 255) / 256, 256>>>(lstm_Wih);

    // q/kq/v in fp32 (argmax-sensitive)
    {
        dim3 g1(HH / 128, BB / 128);
        sgemm_kernel<<<g1, 256>>>(BB, HH, DD, x_t, DD, Wq, DD, 1, p_q, HH, nullptr);
        dim3 g2(DD / 128, BB / 128);
        sgemm_kernel<<<g2, 256>>>(BB, DD, HH, p_q, HH, Wk, DD, 0, p_kq, DD, nullptr);
        sgemm_kernel<<<g2, 256>>>(BB, DD, DD, x_t, DD, Wv, DD, 1, p_v, DD, bv);
    }

    select_idx_kernel<<<BB, NSLOT>>>(slots, filled);
    {
        size_t tot = (size_t)BB * NSLOT * DD;
        update_write_kernel<<<(unsigned)((tot + 255) / 256), 256>>>(
            slots, cum, delta, filled, x_t, out);
    }

    // xg = mem_seq @ WihP.T + (bih+bhh)    (tf32 warp MMA)
    launch_tc(NSLOT * BB, G4, FEATP, p_mem, FEATP, p_wihp, FEATP,
              p_xg, G4, p_bias, nullptr);

    // slot-LSTM recurrence
    for (int n = 0; n < NSLOT; n++) {
        const float* xg_n = p_xg + (size_t)n * BB * G4;
        launch_tc(BB, G4, HH, p_h, HH, lstm_Whh, HH, p_gates, G4, nullptr, xg_n);
        step_pointwise_kernel<<<(BB * HH + 255) / 256, 256>>>();
    }

    // outer LSTM
    launch_tc(BB, G4, DD, x_t, DD, W_ih, DD + HH, p_gates, G4, b_ih, nullptr);
    launch_tc(BB, G4, HH, p_h, HH, W_ih + DD, DD + HH, p_gates, G4, nullptr, p_gates);
    launch_tc(BB, G4, HH, h_lstm, HH, W_hh, HH, p_gates, G4, nullptr, p_gates);
    outer_pointwise_kernel<<<(BB * HH + 255) / 256, 256>>>(c_lstm, out);
}

// round 6
// speedup vs baseline: 8.1548x; 1.0600x over previous
#include <cuda_runtime.h>
#include <math.h>
#include <stdint.h>

#define BB    2048
#define DD    256
#define HH    512
#define NSLOT 64
#define FEAT  513
#define FEATP 544
#define G4    2048

#define OFF_H      ((size_t)0)
#define OFF_C      ((size_t)1048576)
#define OFF_HMEM   ((size_t)2097152)
#define OFF_SLOTS  ((size_t)3145728)
#define OFF_CUM    ((size_t)36700160)
#define OFF_DELTA  ((size_t)70254592)
#define OFF_FILLED ((size_t)70385664)

// ------------------------------- scratch ------------------------------------
__device__ float g_q[BB * HH];        // tf32-truncated q
__device__ float g_kq[BB * DD];
__device__ float g_v[BB * DD];
__device__ int   g_idx[BB];
__device__ float g_bias[G4];          // permuted bih+bhh (fp32)
__device__ float g_biaso[G4];         // permuted outer b_ih (fp32)
__device__ float g_wihp[(size_t)G4 * FEATP];   // permuted+padded+trunc lstm_Wih
__device__ float g_whhp[(size_t)G4 * HH];      // permuted+trunc lstm_Whh
__device__ float g_wihop[(size_t)G4 * 768];    // permuted+trunc W_ih
__device__ float g_whhop[(size_t)G4 * HH];     // permuted+trunc W_hh
__device__ float g_xtf[BB * DD];               // trunc x
__device__ float g_hltf[BB * HH];              // trunc h_lstm
__device__ float g_wqtf[HH * DD];
__device__ float g_wkT[DD * HH];               // trunc transpose of Wk
__device__ float g_wvtf[DD * DD];
__device__ float g_mem[(size_t)NSLOT * BB * FEATP];  // trunc mem_seq [n][b][f]
__device__ float g_xg[(size_t)NSLOT * BB * G4];      // permuted xg [n][b][pcol]
__device__ float g_htf0[BB * HH];              // trunc h ping
__device__ float g_htf1[BB * HH];              // trunc h pong
__device__ float g_c[BB * HH];                 // slot-LSTM cell (fp32)
__device__ int   g_fmode;

__device__ __forceinline__ uint32_t f2tf(float x) {
    uint32_t r;
    asm("cvt.rna.tf32.f32 %0, %1;" : "=r"(r) : "f"(x));
    return r;
}
__device__ __forceinline__ float tff(float x) { return __uint_as_float(f2tf(x)); }

__device__ __forceinline__ float sigf(float x) { return 1.0f / (1.0f + __expf(-x)); }
__device__ __forceinline__ float tanh_fast(float x) {
    float t = __expf(-2.0f * fabsf(x));
    float r = (1.0f - t) / (1.0f + t);
    return copysignf(r, x);
}

__device__ __forceinline__ int read_filled(const void* p, size_t i, int m) {
    if (m == 0) return ((const float*)p)[i] != 0.0f;
    if (m == 1) return ((const int*)p)[i] != 0;
    if (m == 2) return ((const unsigned char*)p)[i] != 0;
    return ((const unsigned short*)p)[i] != 0;
}

// ----------------------------- PTX helpers ----------------------------------
__device__ __forceinline__ uint32_t smem_u32(const void* p) {
    uint32_t a;
    asm("{ .reg .u64 t; cvta.to.shared.u64 t, %1; cvt.u32.u64 %0, t; }" : "=r"(a) : "l"(p));
    return a;
}
__device__ __forceinline__ void cpasync16(uint32_t dst, const void* src) {
    asm volatile("cp.async.cg.shared.global [%0], [%1], 16;\n" :: "r"(dst), "l"(src));
}
#define CP_COMMIT() asm volatile("cp.async.commit_group;\n" ::: "memory")
#define CP_WAIT1()  asm volatile("cp.async.wait_group 1;\n" ::: "memory")
#define CP_WAIT0()  asm volatile("cp.async.wait_group 0;\n" ::: "memory")

__device__ __forceinline__ void mma8(float* c, const uint32_t* A, const uint32_t* B) {
    asm volatile(
        "mma.sync.aligned.m16n8k8.row.col.f32.tf32.tf32.f32 "
        "{%0,%1,%2,%3}, {%4,%5,%6,%7}, {%8,%9}, {%0,%1,%2,%3};"
        : "+f"(c[0]), "+f"(c[1]), "+f"(c[2]), "+f"(c[3])
        : "r"(A[0]), "r"(A[1]), "r"(A[2]), "r"(A[3]), "r"(B[0]), "r"(B[1]));
}

// ------------------------- tf32 warp-MMA GEMM -------------------------------
// All GEMM inputs are PRE-TRUNCATED to tf32. C = A[M,K] @ W[N,K]^T (+bias)(+Cin).
// mode 0: plain store (optional tf32-truncated store)
// mode 1: fused slot-LSTM step epilogue (gates permuted 4j+t)
// mode 2: segmented-K outer LSTM (K=1280) + fused epilogue
#define PADK 36
#define TILE_FLOATS 4608                 // 128 * PADK
#define BUF_FLOATS  9216
#define SMEM_DYN    (2 * BUF_FLOATS * 4) // 73728 B; gates tile 128*132*4=67584 fits

struct GArgs {
    int mode, K, lda, ldw, ldc, trunc_out;
    const float *A, *A2, *A3, *W, *W2, *bias, *Cin, *c_in;
    float *C, *c_out, *h_full, *h_tf;
};

__device__ __forceinline__ void load_stage(uint32_t smb, const GArgs& a,
                                           int bm, int bn, int k0, int tid, int buf) {
    const uint32_t base = smb + (uint32_t)buf * BUF_FLOATS * 4;
    const float* Asrc; int lda, ka;
    if (a.mode == 2) {
        if (k0 < 256)      { Asrc = a.A;  lda = 256; ka = k0; }
        else if (k0 < 768) { Asrc = a.A2; lda = 512; ka = k0 - 256; }
        else               { Asrc = a.A3; lda = 512; ka = k0 - 768; }
    } else { Asrc = a.A; lda = a.lda; ka = k0; }
    const float* Wsrc; int ldw, kw;
    if (a.mode == 2) {
        if (k0 < 768) { Wsrc = a.W;  ldw = 768; kw = k0; }
        else          { Wsrc = a.W2; ldw = 512; kw = k0 - 768; }
    } else { Wsrc = a.W; ldw = a.ldw; kw = k0; }
#pragma unroll
    for (int i = 0; i < 4; i++) {
        int idx = tid + i * 256;
        int r = idx >> 3, c = idx & 7;
        cpasync16(base + (uint32_t)(r * PADK + c * 4) * 4,
                  Asrc + (size_t)(bm + r) * lda + ka + c * 4);
    }
#pragma unroll
    for (int i = 0; i < 4; i++) {
        int idx = tid + i * 256;
        int r = idx >> 3, c = idx & 7;
        cpasync16(base + TILE_FLOATS * 4 + (uint32_t)(r * PADK + c * 4) * 4,
                  Wsrc + (size_t)(bn + r) * ldw + kw + c * 4);
    }
}

__global__ void __launch_bounds__(256) mma_gemm_kernel(const GArgs a) {
    extern __shared__ float sm[];
    const uint32_t smb = smem_u32(sm);

    const int tid = threadIdx.x;
    const int wid = tid >> 5, lane = tid & 31;
    const int wm = wid & 3, wn = wid >> 2;
    const int gid = lane >> 2, tg = lane & 3;
    const int bm = blockIdx.y * 128;
    const int bn = blockIdx.x * 128;

    float acc[2][8][4];
#pragma unroll
    for (int mt = 0; mt < 2; mt++)
#pragma unroll
        for (int nt = 0; nt < 8; nt++)
#pragma unroll
            for (int e = 0; e < 4; e++) acc[mt][nt][e] = 0.0f;

    const int KT = a.K >> 5;
    load_stage(smb, a, bm, bn, 0, tid, 0);
    CP_COMMIT();

    for (int kt = 0; kt < KT; kt++) {
        const int cur = kt & 1;
        if (kt + 1 < KT) {
            load_stage(smb, a, bm, bn, (kt + 1) * 32, tid, cur ^ 1);
            CP_COMMIT();
            CP_WAIT1();
        } else {
            CP_WAIT0();
        }
        __syncthreads();

        const float* As = sm + cur * BUF_FLOATS;
        const float* Bs = As + TILE_FLOATS;
#pragma unroll
        for (int k8 = 0; k8 < 4; k8++) {
            const int kb = k8 * 8;
            uint32_t af[2][4];
#pragma unroll
            for (int mt = 0; mt < 2; mt++) {
                int r0 = wm * 32 + mt * 16 + gid;
                af[mt][0] = __float_as_uint(As[r0 * PADK + kb + tg]);
                af[mt][1] = __float_as_uint(As[(r0 + 8) * PADK + kb + tg]);
                af[mt][2] = __float_as_uint(As[r0 * PADK + kb + tg + 4]);
                af[mt][3] = __float_as_uint(As[(r0 + 8) * PADK + kb + tg + 4]);
            }
            uint32_t bf[8][2];
#pragma unroll
            for (int nt = 0; nt < 8; nt++) {
                int n0 = wn * 64 + nt * 8 + gid;
                bf[nt][0] = __float_as_uint(Bs[n0 * PADK + kb + tg]);
                bf[nt][1] = __float_as_uint(Bs[n0 * PADK + kb + tg + 4]);
            }
#pragma unroll
            for (int mt = 0; mt < 2; mt++)
#pragma unroll
                for (int nt = 0; nt < 8; nt++)
                    mma8(acc[mt][nt], af[mt], bf[nt]);
        }
        __syncthreads();
    }

    if (a.mode == 0) {
#pragma unroll
        for (int mt = 0; mt < 2; mt++) {
            const size_t r0 = (size_t)bm + wm * 32 + mt * 16 + gid;
            const size_t r1 = r0 + 8;
#pragma unroll
            for (int nt = 0; nt < 8; nt++) {
                const int col = bn + wn * 64 + nt * 8 + tg * 2;
                float2 v0 = make_float2(acc[mt][nt][0], acc[mt][nt][1]);
                float2 v1 = make_float2(acc[mt][nt][2], acc[mt][nt][3]);
                if (a.bias) {
                    float2 b2 = *(const float2*)(a.bias + col);
                    v0.x += b2.x; v0.y += b2.y; v1.x += b2.x; v1.y += b2.y;
                }
                if (a.Cin) {
                    float2 c0 = *(const float2*)(a.Cin + r0 * a.ldc + col);
                    float2 c1 = *(const float2*)(a.Cin + r1 * a.ldc + col);
                    v0.x += c0.x; v0.y += c0.y; v1.x += c1.x; v1.y += c1.y;
                }
                if (a.trunc_out) {
                    v0.x = tff(v0.x); v0.y = tff(v0.y);
                    v1.x = tff(v1.x); v1.y = tff(v1.y);
                }
                *(float2*)(a.C + r0 * a.ldc + col) = v0;
                *(float2*)(a.C + r1 * a.ldc + col) = v1;
            }
        }
    } else {
        // fused LSTM epilogue: gates (permuted 4j+t) -> smem -> pointwise
        float* gsm = sm;
#pragma unroll
        for (int mt = 0; mt < 2; mt++) {
            const int lr0 = wm * 32 + mt * 16 + gid;
            const int lr1 = lr0 + 8;
#pragma unroll
            for (int nt = 0; nt < 8; nt++) {
                const int lc = wn * 64 + nt * 8 + tg * 2;
                float2 v0 = make_float2(acc[mt][nt][0], acc[mt][nt][1]);
                float2 v1 = make_float2(acc[mt][nt][2], acc[mt][nt][3]);
                if (a.bias) {
                    float2 b2 = *(const float2*)(a.bias + bn + lc);
                    v0.x += b2.x; v0.y += b2.y; v1.x += b2.x; v1.y += b2.y;
                }
                if (a.Cin) {
                    float2 c0 = *(const float2*)(a.Cin + (size_t)(bm + lr0) * a.ldc + bn + lc);
                    float2 c1 = *(const float2*)(a.Cin + (size_t)(bm + lr1) * a.ldc + bn + lc);
                    v0.x += c0.x; v0.y += c0.y; v1.x += c1.x; v1.y += c1.y;
                }
                *(float2*)&gsm[lr0 * 132 + lc] = v0;
                *(float2*)&gsm[lr1 * 132 + lc] = v1;
            }
        }
        __syncthreads();
        const int jb = bn >> 2;
#pragma unroll
        for (int it = 0; it < 16; it++) {
            int idx = tid + it * 256;
            int row = idx >> 5, u = idx & 31;
            float4 gt = *(float4*)&gsm[row * 132 + 4 * u];
            float ii = sigf(gt.x), ff = sigf(gt.y);
            float gg = tanh_fast(gt.z), oo = sigf(gt.w);
            size_t e = (size_t)(bm + row) * HH + jb + u;
            float c_new = ff * a.c_in[e] + ii * gg;
            float h_new = oo * tanh_fast(c_new);
            a.c_out[e] = c_new;
            if (a.h_full) a.h_full[e] = h_new;
            if (a.h_tf)   a.h_tf[e] = tff(h_new);
        }
    }
}

static void launch_g(const GArgs& a, int M, int N) {
    static int attr_set = 0;
    if (!attr_set) {
        cudaFuncSetAttribute(mma_gemm_kernel,
                             cudaFuncAttributeMaxDynamicSharedMemorySize, SMEM_DYN);
        attr_set = 1;
    }
    dim3 grid(N / 128, M / 128);
    mma_gemm_kernel<<<grid, 256, SMEM_DYN>>>(a);
}

// ------------------------------ prep kernels --------------------------------
__device__ __forceinline__ int porig(int p) { return ((p & 3) << 9) | (p >> 2); }

#define PR0 ((size_t)1114112)            // wihp  2048*544
#define PR1 (PR0 + 1048576)              // whhp  2048*512
#define PR2 (PR1 + 1572864)              // wihop 2048*768
#define PR3 (PR2 + 1048576)              // whhop 2048*512
#define PR4 (PR3 + 524288)               // xtf
#define PR5 (PR4 + 1048576)              // hltf
#define PR6 (PR5 + 131072)               // wqtf
#define PR7 (PR6 + 131072)               // wkT
#define PR8 (PR7 + 65536)                // wvtf
#define PR9 (PR8 + 2048)                 // g_bias
#define PRA (PR9 + 2048)                 // g_biaso

__global__ void prep_kernel(const float* __restrict__ Wih, const float* __restrict__ Whh,
                            const float* __restrict__ bih, const float* __restrict__ bhh,
                            const float* __restrict__ Wiho, const float* __restrict__ Whho,
                            const float* __restrict__ biho,
                            const float* __restrict__ x, const float* __restrict__ hl,
                            const float* __restrict__ Wq, const float* __restrict__ Wk,
                            const float* __restrict__ Wv) {
    size_t e = (size_t)blockIdx.x * blockDim.x + threadIdx.x;
    if (e < PR0) {
        int p = (int)(e / FEATP), k = (int)(e % FEATP);
        g_wihp[e] = (k < FEAT) ? tff(Wih[(size_t)porig(p) * FEAT + k]) : 0.0f;
    } else if (e < PR1) {
        size_t i = e - PR0; int p = (int)(i >> 9), k = (int)(i & 511);
        g_whhp[i] = tff(Whh[(size_t)porig(p) * 512 + k]);
    } else if (e < PR2) {
        size_t i = e - PR1; int p = (int)(i / 768), k = (int)(i % 768);
        g_wihop[i] = tff(Wiho[(size_t)porig(p) * 768 + k]);
    } else if (e < PR3) {
        size_t i = e - PR2; int p = (int)(i >> 9), k = (int)(i & 511);
        g_whhop[i] = tff(Whho[(size_t)porig(p) * 512 + k]);
    } else if (e < PR4) {
        size_t i = e - PR3; g_xtf[i] = tff(x[i]);
    } else if (e < PR5) {
        size_t i = e - PR4; g_hltf[i] = tff(hl[i]);
    } else if (e < PR6) {
        size_t i = e - PR5; g_wqtf[i] = tff(Wq[i]);
    } else if (e < PR7) {
        size_t i = e - PR6; int d = (int)(i >> 9), h = (int)(i & 511);
        g_wkT[i] = tff(Wk[h * 256 + d]);
    } else if (e < PR8) {
        size_t i = e - PR7; g_wvtf[i] = tff(Wv[i]);
    } else if (e < PR9) {
        int p = (int)(e - PR8); int o = porig(p);
        g_bias[p] = bih[o] + bhh[o];
    } else if (e < PRA) {
        int p = (int)(e - PR9);
        g_biaso[p] = biho[porig(p)];
    }
}

__global__ void zero_hc_kernel() {
    int e = blockIdx.x * blockDim.x + threadIdx.x;
    if (e < BB * HH) { g_htf0[e] = 0.0f; g_c[e] = 0.0f; }
}

__global__ void detect_filled_kernel(const unsigned int* __restrict__ w) {
    __shared__ int flags[3];
    if (threadIdx.x < 3) flags[threadIdx.x] = 0;
    __syncthreads();
    for (int i = threadIdx.x; i < (BB * NSLOT) / 4; i += blockDim.x) {
        unsigned v = w[i];
        if (v == 0x3F800000u)      atomicOr(&flags[0], 1);
        else if (v == 0x3F803F80u) atomicOr(&flags[1], 1);
        else if (v > 1u)           atomicOr(&flags[2], 1);
    }
    __syncthreads();
    if (threadIdx.x == 0) {
        int m;
        if (flags[1])      m = 3;
        else if (flags[0]) m = 0;
        else if (flags[2]) m = 2;
        else               m = 1;
        g_fmode = m;
    }
}

__global__ void select_idx_kernel(const float* __restrict__ slots,
                                  const void* __restrict__ filled) {
    const int b = blockIdx.x;
    const int t = threadIdx.x;
    __shared__ float kq_s[DD];
    __shared__ float sims[NSLOT];
    __shared__ int   emp[NSLOT];
    for (int d = t; d < DD; d += NSLOT) kq_s[d] = g_kq[b * DD + d];
    __syncthreads();
    const float* sp = slots + ((size_t)b * NSLOT + t) * DD;
    float s = 0.0f;
    for (int d = 0; d < DD; d++) s = fmaf(sp[d], kq_s[d], s);
    sims[t] = s;
    emp[t]  = !read_filled(filled, (size_t)b * NSLOT + t, g_fmode);
    __syncthreads();
    if (t == 0) {
        int idx = -1;
        for (int n = 0; n < NSLOT; n++) if (emp[n]) { idx = n; break; }
        if (idx < 0) {
            float best = sims[0]; idx = 0;
            for (int n = 1; n < NSLOT; n++) if (sims[n] > best) { best = sims[n]; idx = n; }
        }
        g_idx[b] = idx;
    }
}

__global__ void update_write_kernel(const float* __restrict__ slots,
                                    const float* __restrict__ cum,
                                    const float* __restrict__ delta,
                                    const void* __restrict__ filled,
                                    const float* __restrict__ x,
                                    float* __restrict__ out) {
    size_t e = (size_t)blockIdx.x * blockDim.x + threadIdx.x;
    if (e >= (size_t)BB * NSLOT * DD) return;
    int d = (int)(e % DD);
    size_t bn = e / DD;
    int n = (int)(bn % NSLOT);
    int b = (int)(bn / NSLOT);
    int idx = g_idx[b];

    float xv = x[b * DD + d];
    float sl = slots[e];
    float cf = cum[e] + xv;
    if (n == idx) { sl = g_v[b * DD + d]; cf = xv; }

    out[OFF_SLOTS + e] = sl;
    out[OFF_CUM + e]   = cf;

    size_t mbase = ((size_t)n * BB + b) * FEATP;
    g_mem[mbase + d]      = tff(sl);
    g_mem[mbase + DD + d] = tff(cf);
    if (d < FEATP - FEAT) g_mem[mbase + FEAT + d] = 0.0f;
    if (d == 0) {
        float dt = (n == idx) ? 0.0f : delta[bn] + 1.0f;
        out[OFF_DELTA + bn] = dt;
        g_mem[mbase + 2 * DD] = tff(dt);
        int fl = (n == idx) ? 1 : read_filled(filled, bn, g_fmode);
        out[OFF_FILLED + bn] = fl ? 1.0f : 0.0f;
    }
}

// --------------------------------- launch -----------------------------------
extern "C" void kernel_launch(void* const* d_in, const int* in_sizes, int n_in,
                              void* d_out, int out_size) {
    const float* x_t      = (const float*)d_in[0];
    const float* h_lstm   = (const float*)d_in[1];
    const float* c_lstm   = (const float*)d_in[2];
    const float* slots    = (const float*)d_in[4];
    const float* cum      = (const float*)d_in[5];
    const float* delta    = (const float*)d_in[6];
    const void*  filled   = (const void*)d_in[7];
    const float* Wq       = (const float*)d_in[8];
    const float* Wk       = (const float*)d_in[9];
    const float* Wv       = (const float*)d_in[10];
    const float* bv       = (const float*)d_in[11];
    const float* lstm_Wih = (const float*)d_in[12];
    const float* lstm_Whh = (const float*)d_in[13];
    const float* lstm_bih = (const float*)d_in[14];
    const float* lstm_bhh = (const float*)d_in[15];
    const float* W_ih     = (const float*)d_in[16];
    const float* b_ih     = (const float*)d_in[17];
    const float* W_hh     = (const float*)d_in[18];
    float* out = (float*)d_out;

    float *p_q, *p_kq, *p_v, *p_mem, *p_xg, *p_c, *p_bias, *p_biaso;
    float *p_wihp, *p_whhp, *p_wihop, *p_whhop, *p_xtf, *p_hltf, *p_wqtf, *p_wkT, *p_wvtf;
    float *p_h0, *p_h1;
    cudaGetSymbolAddress((void**)&p_q, g_q);
    cudaGetSymbolAddress((void**)&p_kq, g_kq);
    cudaGetSymbolAddress((void**)&p_v, g_v);
    cudaGetSymbolAddress((void**)&p_mem, g_mem);
    cudaGetSymbolAddress((void**)&p_xg, g_xg);
    cudaGetSymbolAddress((void**)&p_c, g_c);
    cudaGetSymbolAddress((void**)&p_bias, g_bias);
    cudaGetSymbolAddress((void**)&p_biaso, g_biaso);
    cudaGetSymbolAddress((void**)&p_wihp, g_wihp);
    cudaGetSymbolAddress((void**)&p_whhp, g_whhp);
    cudaGetSymbolAddress((void**)&p_wihop, g_wihop);
    cudaGetSymbolAddress((void**)&p_whhop, g_whhop);
    cudaGetSymbolAddress((void**)&p_xtf, g_xtf);
    cudaGetSymbolAddress((void**)&p_hltf, g_hltf);
    cudaGetSymbolAddress((void**)&p_wqtf, g_wqtf);
    cudaGetSymbolAddress((void**)&p_wkT, g_wkT);
    cudaGetSymbolAddress((void**)&p_wvtf, g_wvtf);
    cudaGetSymbolAddress((void**)&p_h0, g_htf0);
    cudaGetSymbolAddress((void**)&p_h1, g_htf1);

    detect_filled_kernel<<<1, 256>>>((const unsigned int*)filled);
    zero_hc_kernel<<<(BB * HH + 255) / 256, 256>>>();
    prep_kernel<<<(unsigned)((PRA + 255) / 256), 256>>>(
        lstm_Wih, lstm_Whh, lstm_bih, lstm_bhh,
        W_ih, W_hh, b_ih, x_t, h_lstm, Wq, Wk, Wv);

    GArgs a;
    // q = x @ Wq.T  (trunc store, feeds kq)
    a = {}; a.mode = 0; a.K = 256; a.lda = 256; a.ldw = 256; a.ldc = 512;
    a.trunc_out = 1; a.A = p_xtf; a.W = p_wqtf; a.C = p_q;
    launch_g(a, BB, HH);
    // kq = q @ Wk   (WkT pre-transposed)
    a = {}; a.mode = 0; a.K = 512; a.lda = 512; a.ldw = 512; a.ldc = 256;
    a.A = p_q; a.W = p_wkT; a.C = p_kq;
    launch_g(a, BB, DD);
    // v = x @ Wv.T + bv
    a = {}; a.mode = 0; a.K = 256; a.lda = 256; a.ldw = 256; a.ldc = 256;
    a.A = p_xtf; a.W = p_wvtf; a.bias = bv; a.C = p_v;
    launch_g(a, BB, DD);

    select_idx_kernel<<<BB, NSLOT>>>(slots, filled);
    {
        size_t tot = (size_t)BB * NSLOT * DD;
        update_write_kernel<<<(unsigned)((tot + 255) / 256), 256>>>(
            slots, cum, delta, filled, x_t, out);
    }

    // xg = mem_seq @ WihP.T + biasP   (permuted gate layout)
    a = {}; a.mode = 0; a.K = FEATP; a.lda = FEATP; a.ldw = FEATP; a.ldc = G4;
    a.A = p_mem; a.W = p_wihp; a.bias = p_bias; a.C = p_xg;
    launch_g(a, NSLOT * BB, G4);

    // slot-LSTM recurrence with fused pointwise; h ping-pong
    for (int n = 0; n < NSLOT; n++) {
        a = {}; a.mode = 1; a.K = HH; a.lda = HH; a.ldw = HH; a.ldc = G4;
        a.A = (n & 1) ? p_h1 : p_h0;
        a.W = p_whhp;
        a.Cin = p_xg + (size_t)n * BB * G4;
        a.c_in = p_c; a.c_out = p_c;
        a.h_tf = (n & 1) ? p_h0 : p_h1;
        a.h_full = (n == NSLOT - 1) ? (out + OFF_HMEM) : nullptr;
        launch_g(a, BB, G4);
    }

    // outer LSTM: segmented K = [x(256) | h_mem(512) | h_lstm(512)], fused epilogue
    a = {}; a.mode = 2; a.K = 1280; a.ldc = G4;
    a.A = p_xtf; a.A2 = p_h0; a.A3 = p_hltf;     // final h in buf0 (n=63 writes h0)
    a.W = p_wihop; a.W2 = p_whhop; a.bias = p_biaso;
    a.c_in = c_lstm; a.c_out = out + OFF_C; a.h_full = out + OFF_H;
    launch_g(a, BB, G4);
}